// round 1
// baseline (speedup 1.0000x reference)
#include <cuda_runtime.h>
#include <math.h>

// Problem constants
#define BATCH 4
#define CDIM  512
#define TDIM  2048
#define NCB   4096
#define HH    4
// combined scale: 1/(sqrt(d)*sqrt(h)) = 1/(sqrt(128)*2)
#define CSCALE 0.04419417382415922f

// GEMM tiling
#define BM 128
#define BN 128
#define BK 16
#define TM 8
#define TN 8
#define NTHR 256

// ---------------- scratch (device globals; no runtime allocation) -----------
__device__ float g_Kp[(size_t)NCB * CDIM];          // K' = codebook@Wk + bk   [N,C]
__device__ float g_V [(size_t)NCB * CDIM];          // V  = codebook@Wv + bv   [N,C]
__device__ float g_Qg[(size_t)BATCH * TDIM * CDIM]; // gated Q                 [B,T,C]
__device__ float g_cg[(size_t)BATCH * TDIM * HH];   // head gates              [B,T,H]
__device__ int   g_idx[(size_t)BATCH * TDIM];
__device__ float g_pmax[16 * BATCH * TDIM];
__device__ int   g_pidx[16 * BATCH * TDIM];

// ---------------- head-gate projection: cg[b,t,h] = hidden[b,:,t]·Wp[:,h]+bp
__global__ void cg_kernel(const float* __restrict__ hidden,
                          const float* __restrict__ Wp,
                          const float* __restrict__ bp) {
    int b = blockIdx.y;
    int h = threadIdx.x & 3;
    int t = blockIdx.x * 64 + (threadIdx.x >> 2);
    const float* hp = hidden + (size_t)b * CDIM * TDIM + t;
    float acc = 0.f;
    #pragma unroll 8
    for (int ci = 0; ci < CDIM; ci++)
        acc += hp[(size_t)ci * TDIM] * __ldg(&Wp[ci * HH + h]);
    g_cg[((size_t)b * TDIM + t) * HH + h] = acc + bp[h];
}

// ---------------- codebook projections: K' and V (NN GEMM, z selects weight)
__global__ __launch_bounds__(NTHR, 2)
void proj_cb_kernel(const float* __restrict__ cb,
                    const float* __restrict__ Wk, const float* __restrict__ bk,
                    const float* __restrict__ Wv, const float* __restrict__ bv) {
    const float* W    = (blockIdx.z == 0) ? Wk : Wv;
    const float* bias = (blockIdx.z == 0) ? bk : bv;
    float* out        = (blockIdx.z == 0) ? g_Kp : g_V;

    int nBase = blockIdx.y * BM;
    int cBase = blockIdx.x * BN;

    __shared__ float As[BK][BM + 4];
    __shared__ float Bs[BK][BN + 4];

    int tid = threadIdx.x;
    int tx = tid & 15, ty = tid >> 4;
    float acc[TM][TN] = {};

    for (int k0 = 0; k0 < CDIM; k0 += BK) {
        #pragma unroll
        for (int i = 0; i < 2; i++) {
            int idx4 = tid + i * NTHR;
            int r  = idx4 >> 2;
            int kq = (idx4 & 3) * 4;
            float4 v = *(const float4*)(cb + (size_t)(nBase + r) * CDIM + k0 + kq);
            As[kq + 0][r] = v.x; As[kq + 1][r] = v.y;
            As[kq + 2][r] = v.z; As[kq + 3][r] = v.w;
        }
        #pragma unroll
        for (int i = 0; i < 2; i++) {
            int idx4 = tid + i * NTHR;
            int kr = idx4 >> 5;
            int c4 = (idx4 & 31) * 4;
            float4 v = *(const float4*)(W + (size_t)(k0 + kr) * CDIM + cBase + c4);
            *(float4*)&Bs[kr][c4] = v;
        }
        __syncthreads();
        #pragma unroll
        for (int kk = 0; kk < BK; kk++) {
            float a[TM], bb[TN];
            #pragma unroll
            for (int i = 0; i < TM; i++) a[i]  = As[kk][ty * TM + i];
            #pragma unroll
            for (int j = 0; j < TN; j++) bb[j] = Bs[kk][tx * TN + j];
            #pragma unroll
            for (int i = 0; i < TM; i++)
                #pragma unroll
                for (int j = 0; j < TN; j++)
                    acc[i][j] += a[i] * bb[j];
        }
        __syncthreads();
    }
    float bv8[TN];
    #pragma unroll
    for (int j = 0; j < TN; j++) bv8[j] = bias[cBase + tx * TN + j];
    #pragma unroll
    for (int i = 0; i < TM; i++) {
        int n = nBase + ty * TM + i;
        float* op = out + (size_t)n * CDIM + cBase + tx * TN;
        *(float4*)(op)     = make_float4(acc[i][0] + bv8[0], acc[i][1] + bv8[1],
                                         acc[i][2] + bv8[2], acc[i][3] + bv8[3]);
        *(float4*)(op + 4) = make_float4(acc[i][4] + bv8[4], acc[i][5] + bv8[5],
                                         acc[i][6] + bv8[6], acc[i][7] + bv8[7]);
    }
}

// ---------------- gated Q projection: Qg[b,t,c] = (hidden[b,:,t]·Wq[:,c]+bq)*cg*CSCALE
__global__ __launch_bounds__(NTHR, 2)
void qproj_kernel(const float* __restrict__ hidden,
                  const float* __restrict__ Wq, const float* __restrict__ bq) {
    int b = blockIdx.z;
    int tBase = blockIdx.y * BM;
    int cBase = blockIdx.x * BN;
    const float* hp = hidden + (size_t)b * CDIM * TDIM;

    __shared__ float As[BK][BM + 4];
    __shared__ float Bs[BK][BN + 4];

    int tid = threadIdx.x;
    int tx = tid & 15, ty = tid >> 4;
    float acc[TM][TN] = {};

    for (int k0 = 0; k0 < CDIM; k0 += BK) {
        // A tile: hidden is [C,T]; rows t, k = ci.  t is contiguous -> vector load.
        #pragma unroll
        for (int i = 0; i < 2; i++) {
            int idx4 = tid + i * NTHR;
            int kci = idx4 >> 5;          // 0..15
            int t4  = (idx4 & 31) * 4;    // 0..124
            float4 v = *(const float4*)(hp + (size_t)(k0 + kci) * TDIM + tBase + t4);
            *(float4*)&As[kci][t4] = v;
        }
        #pragma unroll
        for (int i = 0; i < 2; i++) {
            int idx4 = tid + i * NTHR;
            int kr = idx4 >> 5;
            int c4 = (idx4 & 31) * 4;
            float4 v = *(const float4*)(Wq + (size_t)(k0 + kr) * CDIM + cBase + c4);
            *(float4*)&Bs[kr][c4] = v;
        }
        __syncthreads();
        #pragma unroll
        for (int kk = 0; kk < BK; kk++) {
            float a[TM], bb[TN];
            #pragma unroll
            for (int i = 0; i < TM; i++) a[i]  = As[kk][ty * TM + i];
            #pragma unroll
            for (int j = 0; j < TN; j++) bb[j] = Bs[kk][tx * TN + j];
            #pragma unroll
            for (int i = 0; i < TM; i++)
                #pragma unroll
                for (int j = 0; j < TN; j++)
                    acc[i][j] += a[i] * bb[j];
        }
        __syncthreads();
    }
    int h = cBase >> 7;   // whole 128-wide tile sits in one head
    float bv8[TN];
    #pragma unroll
    for (int j = 0; j < TN; j++) bv8[j] = bq[cBase + tx * TN + j];
    #pragma unroll
    for (int i = 0; i < TM; i++) {
        int t = tBase + ty * TM + i;
        float g = g_cg[((size_t)b * TDIM + t) * HH + h] * CSCALE;
        float* op = g_Qg + ((size_t)b * TDIM + t) * CDIM + cBase + tx * TN;
        *(float4*)(op)     = make_float4((acc[i][0] + bv8[0]) * g, (acc[i][1] + bv8[1]) * g,
                                         (acc[i][2] + bv8[2]) * g, (acc[i][3] + bv8[3]) * g);
        *(float4*)(op + 4) = make_float4((acc[i][4] + bv8[4]) * g, (acc[i][5] + bv8[5]) * g,
                                         (acc[i][6] + bv8[6]) * g, (acc[i][7] + bv8[7]) * g);
    }
}

// ---------------- main GEMM: logits[b,n,t] = K'[n,:]·Qg[b,t,:]  (NT, both K-major)
__global__ __launch_bounds__(NTHR, 2)
void gemm_logits_kernel(float* __restrict__ out) {
    int b = blockIdx.z;
    int nBase = blockIdx.y * BM;
    int tBase = blockIdx.x * BN;
    const float* Bp = g_Qg + (size_t)b * TDIM * CDIM;

    __shared__ float As[BK][BM + 4];
    __shared__ float Bs[BK][BN + 4];

    int tid = threadIdx.x;
    int tx = tid & 15, ty = tid >> 4;
    float acc[TM][TN] = {};

    for (int k0 = 0; k0 < CDIM; k0 += BK) {
        #pragma unroll
        for (int i = 0; i < 2; i++) {
            int idx4 = tid + i * NTHR;
            int r  = idx4 >> 2;
            int kq = (idx4 & 3) * 4;
            float4 v = *(const float4*)(g_Kp + (size_t)(nBase + r) * CDIM + k0 + kq);
            As[kq + 0][r] = v.x; As[kq + 1][r] = v.y;
            As[kq + 2][r] = v.z; As[kq + 3][r] = v.w;
        }
        #pragma unroll
        for (int i = 0; i < 2; i++) {
            int idx4 = tid + i * NTHR;
            int r  = idx4 >> 2;
            int kq = (idx4 & 3) * 4;
            float4 v = *(const float4*)(Bp + (size_t)(tBase + r) * CDIM + k0 + kq);
            Bs[kq + 0][r] = v.x; Bs[kq + 1][r] = v.y;
            Bs[kq + 2][r] = v.z; Bs[kq + 3][r] = v.w;
        }
        __syncthreads();
        #pragma unroll
        for (int kk = 0; kk < BK; kk++) {
            float a[TM], bb[TN];
            #pragma unroll
            for (int i = 0; i < TM; i++) a[i]  = As[kk][ty * TM + i];
            #pragma unroll
            for (int j = 0; j < TN; j++) bb[j] = Bs[kk][tx * TN + j];
            #pragma unroll
            for (int i = 0; i < TM; i++)
                #pragma unroll
                for (int j = 0; j < TN; j++)
                    acc[i][j] += a[i] * bb[j];
        }
        __syncthreads();
    }
    float* op = out + (size_t)b * NCB * TDIM;
    #pragma unroll
    for (int i = 0; i < TM; i++) {
        int n = nBase + ty * TM + i;
        float* row = op + (size_t)n * TDIM + tBase + tx * TN;
        *(float4*)(row)     = make_float4(acc[i][0], acc[i][1], acc[i][2], acc[i][3]);
        *(float4*)(row + 4) = make_float4(acc[i][4], acc[i][5], acc[i][6], acc[i][7]);
    }
}

// ---------------- argmax over N (split across 16 n-chunks for occupancy) ----
__global__ void argmax_part_kernel(const float* __restrict__ logits) {
    int b = blockIdx.y, z = blockIdx.z;
    int t = blockIdx.x * 256 + threadIdx.x;
    const float* p = logits + (size_t)b * NCB * TDIM + (size_t)z * 256 * TDIM + t;
    float best = -INFINITY; int bi = 0;
    #pragma unroll 4
    for (int n = 0; n < 256; n++) {
        float x = p[(size_t)n * TDIM];
        if (x > best) { best = x; bi = n; }
    }
    g_pmax[(z * BATCH + b) * TDIM + t] = best;
    g_pidx[(z * BATCH + b) * TDIM + t] = z * 256 + bi;
}

__global__ void argmax_final_kernel(float* __restrict__ idx_out) {
    int b = blockIdx.y;
    int t = blockIdx.x * 256 + threadIdx.x;
    float best = -INFINITY; int bi = 0;
    #pragma unroll
    for (int z = 0; z < 16; z++) {   // ascending z + strict '>' => first max wins
        float x = g_pmax[(z * BATCH + b) * TDIM + t];
        int  ii = g_pidx[(z * BATCH + b) * TDIM + t];
        if (x > best) { best = x; bi = ii; }
    }
    g_idx[b * TDIM + t] = bi;
    idx_out[b * TDIM + t] = (float)bi;
}

// ---------------- z_q gather: z_q[b,c,t] = V[idx[b,t], c] -------------------
__global__ void zq_kernel(float* __restrict__ zq) {
    int b = blockIdx.y;
    int lane = threadIdx.x & 31;
    int cgrp = threadIdx.x >> 5;              // 0..7, each owns 64 c's
    int t = blockIdx.x * 32 + lane;
    int row = g_idx[b * TDIM + t];
    const float* v = g_V + (size_t)row * CDIM;
    float* o = zq + (size_t)b * CDIM * TDIM + t;
    int c0 = cgrp * 64;
    #pragma unroll 8
    for (int c = c0; c < c0 + 64; c++)
        o[(size_t)c * TDIM] = __ldg(&v[c]);
}

// ---------------- launcher --------------------------------------------------
extern "C" void kernel_launch(void* const* d_in, const int* in_sizes, int n_in,
                              void* d_out, int out_size) {
    const float* hidden = (const float*)d_in[0];  // [B,C,T]
    const float* cb     = (const float*)d_in[1];  // [N,C]
    const float* Wq = (const float*)d_in[2]; const float* bq = (const float*)d_in[3];
    const float* Wk = (const float*)d_in[4]; const float* bk = (const float*)d_in[5];
    const float* Wv = (const float*)d_in[6]; const float* bv = (const float*)d_in[7];
    const float* Wp = (const float*)d_in[8]; const float* bp = (const float*)d_in[9];

    float* out        = (float*)d_out;
    float* out_logits = out;                                       // B*N*T
    float* out_idx    = out + (size_t)BATCH * NCB * TDIM;          // B*T
    float* out_zq     = out_idx + (size_t)BATCH * TDIM;            // B*C*T

    // K' and V projections
    proj_cb_kernel<<<dim3(CDIM / BN, NCB / BM, 2), NTHR>>>(cb, Wk, bk, Wv, bv);
    // head gates
    cg_kernel<<<dim3(TDIM / 64, BATCH), 256>>>(hidden, Wp, bp);
    // gated Q
    qproj_kernel<<<dim3(CDIM / BN, TDIM / BM, BATCH), NTHR>>>(hidden, Wq, bq);
    // logits (written straight into d_out in [B,N,T])
    gemm_logits_kernel<<<dim3(TDIM / BN, NCB / BM, BATCH), NTHR>>>(out_logits);
    // argmax over N
    argmax_part_kernel<<<dim3(TDIM / 256, BATCH, 16), 256>>>(out_logits);
    argmax_final_kernel<<<dim3(TDIM / 256, BATCH), 256>>>(out_idx);
    // codebook gather
    zq_kernel<<<dim3(TDIM / 32, BATCH), 256>>>(out_zq);
}

// round 3
// speedup vs baseline: 2.0698x; 2.0698x over previous
#include <cuda_runtime.h>
#include <cuda_bf16.h>
#include <math.h>
#include <stdint.h>

// Problem constants
#define BATCH 4
#define CDIM  512
#define TDIM  2048
#define NCB   4096
#define HH    4
#define KSPLIT (3 * CDIM)          // 1536: [hi|lo|hi] x [hi|hi|lo]
// combined scale: 1/(sqrt(d)*sqrt(h)) = 1/(sqrt(128)*2)
#define CSCALE 0.04419417382415922f

// SIMT GEMM tiling (projections)
#define BM 128
#define BN 128
#define BK 16
#define TM 8
#define TN 8
#define NTHR 256

#define NBLOCKS (NCB / 128)        // 32 partial-argmax slices

// ---------------- scratch (device globals; no runtime allocation) -----------
__device__ __nv_bfloat16 g_KpS[(size_t)NCB * KSPLIT];          // [N,1536] hi|lo|hi
__device__ __nv_bfloat16 g_QgS[(size_t)BATCH * TDIM * KSPLIT]; // [B*T,1536] hi|hi|lo
__device__ float g_V [(size_t)NCB * CDIM];          // V = codebook@Wv + bv   [N,C]
__device__ float g_cg[(size_t)BATCH * TDIM * HH];   // head gates             [B,T,H]
__device__ int   g_idx[(size_t)BATCH * TDIM];
__device__ float g_pmax[NBLOCKS * BATCH * TDIM];
__device__ int   g_pidx[NBLOCKS * BATCH * TDIM];

// ======================= helpers ============================================
#define SMEM_SWIZZLE_128B(off) ((off) ^ (((off) >> 3) & 0x70))
#define CP_ASYNC16(dst, src) \
    asm volatile("cp.async.cg.shared.global [%0], [%1], 16;" :: "r"(dst), "l"(src))
#define CP_ASYNC_COMMIT() asm volatile("cp.async.commit_group;" ::: "memory")

__device__ __forceinline__ uint32_t smem_to_u32(const void* p) {
    uint32_t a;
    asm("{ .reg .u64 t; cvta.to.shared.u64 t, %1; cvt.u32.u64 %0, t; }"
        : "=r"(a) : "l"(p));
    return a;
}
__device__ __forceinline__ void ldsm_x4(uint32_t& r0, uint32_t& r1, uint32_t& r2,
                                        uint32_t& r3, uint32_t addr) {
    asm volatile("ldmatrix.sync.aligned.m8n8.x4.shared.b16 {%0,%1,%2,%3}, [%4];"
                 : "=r"(r0), "=r"(r1), "=r"(r2), "=r"(r3) : "r"(addr));
}
__device__ __forceinline__ void mma16816(float* c, uint32_t a0, uint32_t a1,
                                         uint32_t a2, uint32_t a3,
                                         uint32_t b0, uint32_t b1) {
    asm volatile(
        "mma.sync.aligned.m16n8k16.row.col.f32.bf16.bf16.f32 "
        "{%0,%1,%2,%3}, {%4,%5,%6,%7}, {%8,%9}, {%0,%1,%2,%3};"
        : "+f"(c[0]), "+f"(c[1]), "+f"(c[2]), "+f"(c[3])
        : "r"(a0), "r"(a1), "r"(a2), "r"(a3), "r"(b0), "r"(b1));
}

// bf16 split helper: packs hi/lo pairs
__device__ __forceinline__ void split2bf(float v0, float v1, unsigned& hu, unsigned& lu) {
    __nv_bfloat16 h0 = __float2bfloat16(v0), h1 = __float2bfloat16(v1);
    float r0 = v0 - __bfloat162float(h0), r1 = v1 - __bfloat162float(h1);
    __nv_bfloat16 l0 = __float2bfloat16(r0), l1 = __float2bfloat16(r1);
    __nv_bfloat162 ph = __halves2bfloat162(h0, h1);
    __nv_bfloat162 pl = __halves2bfloat162(l0, l1);
    hu = *reinterpret_cast<unsigned*>(&ph);
    lu = *reinterpret_cast<unsigned*>(&pl);
}

// ---------------- head-gate projection: cg[b,t,h] = hidden[b,:,t]·Wp[:,h]+bp
__global__ void cg_kernel(const float* __restrict__ hidden,
                          const float* __restrict__ Wp,
                          const float* __restrict__ bp) {
    int b = blockIdx.y;
    int h = threadIdx.x & 3;
    int t = blockIdx.x * 64 + (threadIdx.x >> 2);
    const float* hp = hidden + (size_t)b * CDIM * TDIM + t;
    float acc = 0.f;
    #pragma unroll 8
    for (int ci = 0; ci < CDIM; ci++)
        acc += hp[(size_t)ci * TDIM] * __ldg(&Wp[ci * HH + h]);
    g_cg[((size_t)b * TDIM + t) * HH + h] = acc + bp[h];
}

// ---------------- codebook projections: K' (split bf16) and V (fp32) --------
__global__ __launch_bounds__(NTHR, 2)
void proj_cb_kernel(const float* __restrict__ cb,
                    const float* __restrict__ Wk, const float* __restrict__ bk,
                    const float* __restrict__ Wv, const float* __restrict__ bv) {
    const float* W    = (blockIdx.z == 0) ? Wk : Wv;
    const float* bias = (blockIdx.z == 0) ? bk : bv;

    int nBase = blockIdx.y * BM;
    int cBase = blockIdx.x * BN;

    __shared__ float As[BK][BM + 4];
    __shared__ float Bs[BK][BN + 4];

    int tid = threadIdx.x;
    int tx = tid & 15, ty = tid >> 4;
    float acc[TM][TN] = {};

    for (int k0 = 0; k0 < CDIM; k0 += BK) {
        #pragma unroll
        for (int i = 0; i < 2; i++) {
            int idx4 = tid + i * NTHR;
            int r  = idx4 >> 2;
            int kq = (idx4 & 3) * 4;
            float4 v = *(const float4*)(cb + (size_t)(nBase + r) * CDIM + k0 + kq);
            As[kq + 0][r] = v.x; As[kq + 1][r] = v.y;
            As[kq + 2][r] = v.z; As[kq + 3][r] = v.w;
        }
        #pragma unroll
        for (int i = 0; i < 2; i++) {
            int idx4 = tid + i * NTHR;
            int kr = idx4 >> 5;
            int c4 = (idx4 & 31) * 4;
            float4 v = *(const float4*)(W + (size_t)(k0 + kr) * CDIM + cBase + c4);
            *(float4*)&Bs[kr][c4] = v;
        }
        __syncthreads();
        #pragma unroll
        for (int kk = 0; kk < BK; kk++) {
            float a[TM], bb[TN];
            #pragma unroll
            for (int i = 0; i < TM; i++) a[i]  = As[kk][ty * TM + i];
            #pragma unroll
            for (int j = 0; j < TN; j++) bb[j] = Bs[kk][tx * TN + j];
            #pragma unroll
            for (int i = 0; i < TM; i++)
                #pragma unroll
                for (int j = 0; j < TN; j++)
                    acc[i][j] += a[i] * bb[j];
        }
        __syncthreads();
    }
    float bv8[TN];
    #pragma unroll
    for (int j = 0; j < TN; j++) bv8[j] = bias[cBase + tx * TN + j];

    if (blockIdx.z == 1) {          // V: fp32
        #pragma unroll
        for (int i = 0; i < TM; i++) {
            int n = nBase + ty * TM + i;
            float* op = g_V + (size_t)n * CDIM + cBase + tx * TN;
            *(float4*)(op)     = make_float4(acc[i][0] + bv8[0], acc[i][1] + bv8[1],
                                             acc[i][2] + bv8[2], acc[i][3] + bv8[3]);
            *(float4*)(op + 4) = make_float4(acc[i][4] + bv8[4], acc[i][5] + bv8[5],
                                             acc[i][6] + bv8[6], acc[i][7] + bv8[7]);
        }
    } else {                        // K': bf16 split [hi | lo | hi]
        #pragma unroll
        for (int i = 0; i < TM; i++) {
            int n = nBase + ty * TM + i;
            uint4 hu, lu;
            split2bf(acc[i][0] + bv8[0], acc[i][1] + bv8[1], hu.x, lu.x);
            split2bf(acc[i][2] + bv8[2], acc[i][3] + bv8[3], hu.y, lu.y);
            split2bf(acc[i][4] + bv8[4], acc[i][5] + bv8[5], hu.z, lu.z);
            split2bf(acc[i][6] + bv8[6], acc[i][7] + bv8[7], hu.w, lu.w);
            __nv_bfloat16* op = g_KpS + (size_t)n * KSPLIT + cBase + tx * TN;
            *(uint4*)(op)            = hu;   // hi
            *(uint4*)(op + CDIM)     = lu;   // lo
            *(uint4*)(op + 2*CDIM)   = hu;   // hi (dup)
        }
    }
}

// ---------------- gated Q projection → bf16 split [hi | hi | lo] ------------
__global__ __launch_bounds__(NTHR, 2)
void qproj_kernel(const float* __restrict__ hidden,
                  const float* __restrict__ Wq, const float* __restrict__ bq) {
    int b = blockIdx.z;
    int tBase = blockIdx.y * BM;
    int cBase = blockIdx.x * BN;
    const float* hp = hidden + (size_t)b * CDIM * TDIM;

    __shared__ float As[BK][BM + 4];
    __shared__ float Bs[BK][BN + 4];

    int tid = threadIdx.x;
    int tx = tid & 15, ty = tid >> 4;
    float acc[TM][TN] = {};

    for (int k0 = 0; k0 < CDIM; k0 += BK) {
        #pragma unroll
        for (int i = 0; i < 2; i++) {
            int idx4 = tid + i * NTHR;
            int kci = idx4 >> 5;
            int t4  = (idx4 & 31) * 4;
            float4 v = *(const float4*)(hp + (size_t)(k0 + kci) * TDIM + tBase + t4);
            *(float4*)&As[kci][t4] = v;
        }
        #pragma unroll
        for (int i = 0; i < 2; i++) {
            int idx4 = tid + i * NTHR;
            int kr = idx4 >> 5;
            int c4 = (idx4 & 31) * 4;
            float4 v = *(const float4*)(Wq + (size_t)(k0 + kr) * CDIM + cBase + c4);
            *(float4*)&Bs[kr][c4] = v;
        }
        __syncthreads();
        #pragma unroll
        for (int kk = 0; kk < BK; kk++) {
            float a[TM], bb[TN];
            #pragma unroll
            for (int i = 0; i < TM; i++) a[i]  = As[kk][ty * TM + i];
            #pragma unroll
            for (int j = 0; j < TN; j++) bb[j] = Bs[kk][tx * TN + j];
            #pragma unroll
            for (int i = 0; i < TM; i++)
                #pragma unroll
                for (int j = 0; j < TN; j++)
                    acc[i][j] += a[i] * bb[j];
        }
        __syncthreads();
    }
    int h = cBase >> 7;
    float bv8[TN];
    #pragma unroll
    for (int j = 0; j < TN; j++) bv8[j] = bq[cBase + tx * TN + j];
    #pragma unroll
    for (int i = 0; i < TM; i++) {
        int t = tBase + ty * TM + i;
        float g = g_cg[((size_t)b * TDIM + t) * HH + h] * CSCALE;
        uint4 hu, lu;
        split2bf((acc[i][0] + bv8[0]) * g, (acc[i][1] + bv8[1]) * g, hu.x, lu.x);
        split2bf((acc[i][2] + bv8[2]) * g, (acc[i][3] + bv8[3]) * g, hu.y, lu.y);
        split2bf((acc[i][4] + bv8[4]) * g, (acc[i][5] + bv8[5]) * g, hu.z, lu.z);
        split2bf((acc[i][6] + bv8[6]) * g, (acc[i][7] + bv8[7]) * g, hu.w, lu.w);
        __nv_bfloat16* op = g_QgS + ((size_t)b * TDIM + t) * KSPLIT + cBase + tx * TN;
        *(uint4*)(op)          = hu;   // hi
        *(uint4*)(op + CDIM)   = hu;   // hi (dup)
        *(uint4*)(op + 2*CDIM) = lu;   // lo
    }
}

// ============== main GEMM via mma.sync bf16 (K=1536 split) ==================
// CTA tile: 128 (n/codebook = M) x 128 (t = N), BK=64, 3-stage cp.async.
// 8 warps in 2(m) x 4(n); warp tile 64x32. Fused per-128-row argmax partials.
#define MMA_STAGE 32768                       // A 16KB + B 16KB
#define MMA_STAGES 3
#define MMA_SMEM (MMA_STAGES * MMA_STAGE)     // 98304
#define MMA_CHUNKS (KSPLIT / 64)              // 24

__global__ __launch_bounds__(256, 2)
void gemm_logits_mma(float* __restrict__ out) {
    extern __shared__ __align__(1024) char smem[];
    const int tid  = threadIdx.x;
    const int wid  = tid >> 5, lane = tid & 31;
    const int wm   = wid & 1;                 // 0..1  (m half)
    const int wn   = wid >> 1;                // 0..3  (n quarter)
    const int b     = blockIdx.z;
    const int nBase = blockIdx.y * 128;       // codebook rows (M)
    const int tBase = blockIdx.x * 128;       // time cols (N)
    const uint32_t sb = smem_to_u32(smem);

    const char* Abase = (const char*)(g_KpS + (size_t)nBase * KSPLIT);
    const char* Bbase = (const char*)(g_QgS + ((size_t)b * TDIM + tBase) * KSPLIT);
    const size_t ROWB = (size_t)KSPLIT * 2;   // 3072 B per logical row

    float acc[4][4][4] = {};                  // [mi][nj][frag]

    #define ISSUE_LOAD(c) do { \
        int _s = (c) % MMA_STAGES; \
        uint32_t _as = sb + _s * MMA_STAGE; \
        uint32_t _bs = _as + 16384; \
        size_t _ko = (size_t)(c) * 128; \
        _Pragma("unroll") \
        for (int _i = 0; _i < 4; _i++) { \
            int _u = tid + _i * 256; \
            int _r = _u >> 3, _c16 = (_u & 7) * 16; \
            CP_ASYNC16(_as + SMEM_SWIZZLE_128B(_r * 128 + _c16), \
                       Abase + (size_t)_r * ROWB + _ko + _c16); \
        } \
        _Pragma("unroll") \
        for (int _i = 0; _i < 4; _i++) { \
            int _u = tid + _i * 256; \
            int _r = _u >> 3, _c16 = (_u & 7) * 16; \
            CP_ASYNC16(_bs + SMEM_SWIZZLE_128B(_r * 128 + _c16), \
                       Bbase + (size_t)_r * ROWB + _ko + _c16); \
        } \
        CP_ASYNC_COMMIT(); \
    } while (0)

    ISSUE_LOAD(0);
    ISSUE_LOAD(1);

    for (int c = 0; c < MMA_CHUNKS; c++) {
        if (c < MMA_CHUNKS - 1) asm volatile("cp.async.wait_group 1;" ::: "memory");
        else                    asm volatile("cp.async.wait_group 0;" ::: "memory");
        __syncthreads();

        uint32_t As = sb + (c % MMA_STAGES) * MMA_STAGE;
        uint32_t Bs = As + 16384;

        #pragma unroll
        for (int kk = 0; kk < 4; kk++) {
            uint32_t a[4][4];
            #pragma unroll
            for (int mi = 0; mi < 4; mi++) {
                int row = wm * 64 + mi * 16 + (lane & 15);
                int u   = kk * 2 + (lane >> 4);
                ldsm_x4(a[mi][0], a[mi][1], a[mi][2], a[mi][3],
                        As + row * 128 + ((u ^ (row & 7)) << 4));
            }
            uint32_t bf[2][4];
            #pragma unroll
            for (int nf = 0; nf < 2; nf++) {
                int row = wn * 32 + nf * 16 + ((lane >> 4) << 3) + (lane & 7);
                int u   = kk * 2 + ((lane >> 3) & 1);
                ldsm_x4(bf[nf][0], bf[nf][1], bf[nf][2], bf[nf][3],
                        Bs + row * 128 + ((u ^ (row & 7)) << 4));
            }
            #pragma unroll
            for (int mi = 0; mi < 4; mi++)
                #pragma unroll
                for (int nj = 0; nj < 4; nj++)
                    mma16816(acc[mi][nj], a[mi][0], a[mi][1], a[mi][2], a[mi][3],
                             bf[nj >> 1][(nj & 1) * 2], bf[nj >> 1][(nj & 1) * 2 + 1]);
        }
        __syncthreads();
        if (c + 2 < MMA_CHUNKS) ISSUE_LOAD(c + 2);
    }
    #undef ISSUE_LOAD

    __syncthreads();   // stage smem free; safe to alias for argmax below

    // ---- write logits ----
    float* obase = out + (size_t)b * NCB * TDIM + (size_t)nBase * TDIM + tBase;
    #pragma unroll
    for (int mi = 0; mi < 4; mi++) {
        #pragma unroll
        for (int nj = 0; nj < 4; nj++) {
            int r  = wm * 64 + mi * 16 + (lane >> 2);
            int cc = wn * 32 + nj * 8 + 2 * (lane & 3);
            *(float2*)(obase + (size_t)r * TDIM + cc) =
                make_float2(acc[mi][nj][0], acc[mi][nj][1]);
            *(float2*)(obase + (size_t)(r + 8) * TDIM + cc) =
                make_float2(acc[mi][nj][2], acc[mi][nj][3]);
        }
    }

    // ---- fused argmax partial over this CTA's 128 rows ----
    float mv[8]; int mi_[8];
    #pragma unroll
    for (int nj = 0; nj < 4; nj++) {
        #pragma unroll
        for (int cc = 0; cc < 2; cc++) {
            int key = nj * 2 + cc;
            float best = -INFINITY; int bidx = 0;
            #pragma unroll
            for (int mi = 0; mi < 4; mi++) {
                #pragma unroll
                for (int hf = 0; hf < 2; hf++) {
                    float v = acc[mi][nj][hf * 2 + cc];
                    int   ix = nBase + wm * 64 + mi * 16 + (lane >> 2) + hf * 8;
                    if (v > best) { best = v; bidx = ix; }
                }
            }
            mv[key] = best; mi_[key] = bidx;
        }
    }
    #pragma unroll
    for (int off = 4; off < 32; off <<= 1) {
        #pragma unroll
        for (int key = 0; key < 8; key++) {
            float ov = __shfl_xor_sync(0xffffffff, mv[key], off);
            int   oi = __shfl_xor_sync(0xffffffff, mi_[key], off);
            if (ov > mv[key] || (ov == mv[key] && oi < mi_[key])) {
                mv[key] = ov; mi_[key] = oi;
            }
        }
    }
    float* sval = (float*)smem;               // [2][128]
    int*   sidx = (int*)(smem + 2 * 128 * 4); // [2][128]
    if (lane < 4) {
        #pragma unroll
        for (int nj = 0; nj < 4; nj++)
            #pragma unroll
            for (int cc = 0; cc < 2; cc++) {
                int col = wn * 32 + nj * 8 + 2 * lane + cc;
                sval[wm * 128 + col] = mv[nj * 2 + cc];
                sidx[wm * 128 + col] = mi_[nj * 2 + cc];
            }
    }
    __syncthreads();
    if (tid < 128) {
        float v0 = sval[tid],      v1 = sval[128 + tid];
        int   i0 = sidx[tid],      i1 = sidx[128 + tid];
        bool take1 = (v1 > v0) || (v1 == v0 && i1 < i0);
        size_t o = ((size_t)blockIdx.y * BATCH + b) * TDIM + tBase + tid;
        g_pmax[o] = take1 ? v1 : v0;
        g_pidx[o] = take1 ? i1 : i0;
    }
}

// ---------------- final argmax over the 32 slices ---------------------------
__global__ void argmax_final_kernel(float* __restrict__ idx_out) {
    int b = blockIdx.y;
    int t = blockIdx.x * 256 + threadIdx.x;
    float best = -INFINITY; int bi = 0;
    #pragma unroll
    for (int z = 0; z < NBLOCKS; z++) {     // ascending z; strict '>' keeps lowest n
        float x = g_pmax[((size_t)z * BATCH + b) * TDIM + t];
        int  ii = g_pidx[((size_t)z * BATCH + b) * TDIM + t];
        if (x > best || (x == best && ii < bi)) { best = x; bi = ii; }
    }
    g_idx[b * TDIM + t] = bi;
    idx_out[b * TDIM + t] = (float)bi;
}

// ---------------- z_q gather: z_q[b,c,t] = V[idx[b,t], c] -------------------
__global__ void zq_kernel(float* __restrict__ zq) {
    int b = blockIdx.y;
    int lane = threadIdx.x & 31;
    int cgrp = threadIdx.x >> 5;
    int t = blockIdx.x * 32 + lane;
    int row = g_idx[b * TDIM + t];
    const float* v = g_V + (size_t)row * CDIM;
    float* o = zq + (size_t)b * CDIM * TDIM + t;
    int c0 = cgrp * 64;
    #pragma unroll 8
    for (int c = c0; c < c0 + 64; c++)
        o[(size_t)c * TDIM] = __ldg(&v[c]);
}

// ---------------- launcher --------------------------------------------------
extern "C" void kernel_launch(void* const* d_in, const int* in_sizes, int n_in,
                              void* d_out, int out_size) {
    const float* hidden = (const float*)d_in[0];  // [B,C,T]
    const float* cb     = (const float*)d_in[1];  // [N,C]
    const float* Wq = (const float*)d_in[2]; const float* bq = (const float*)d_in[3];
    const float* Wk = (const float*)d_in[4]; const float* bk = (const float*)d_in[5];
    const float* Wv = (const float*)d_in[6]; const float* bv = (const float*)d_in[7];
    const float* Wp = (const float*)d_in[8]; const float* bp = (const float*)d_in[9];

    float* out        = (float*)d_out;
    float* out_logits = out;                                       // B*N*T
    float* out_idx    = out + (size_t)BATCH * NCB * TDIM;          // B*T
    float* out_zq     = out_idx + (size_t)BATCH * TDIM;            // B*C*T

    cudaFuncSetAttribute(gemm_logits_mma,
                         cudaFuncAttributeMaxDynamicSharedMemorySize, MMA_SMEM);

    // K' (split) and V projections
    proj_cb_kernel<<<dim3(CDIM / BN, NCB / BM, 2), NTHR>>>(cb, Wk, bk, Wv, bv);
    // head gates
    cg_kernel<<<dim3(TDIM / 64, BATCH), 256>>>(hidden, Wp, bp);
    // gated Q (split)
    qproj_kernel<<<dim3(CDIM / BN, TDIM / BM, BATCH), NTHR>>>(hidden, Wq, bq);
    // logits on tensor cores (mma.sync) + fused argmax partials
    gemm_logits_mma<<<dim3(TDIM / 128, NCB / 128, BATCH), 256, MMA_SMEM>>>(out_logits);
    // final argmax + z_q gather
    argmax_final_kernel<<<dim3(TDIM / 256, BATCH), 256>>>(out_idx);
    zq_kernel<<<dim3(TDIM / 32, BATCH), 256>>>(out_zq);
}

// round 5
// speedup vs baseline: 2.8834x; 1.3931x over previous
#include <cuda_runtime.h>
#include <cuda_bf16.h>
#include <math.h>
#include <stdint.h>

// Problem constants
#define BATCH 4
#define CDIM  512
#define TDIM  2048
#define NCB   4096
#define HH    4
#define KSPLIT (3 * CDIM)          // 1536
#define CSCALE 0.04419417382415922f   // 1/(sqrt(128)*sqrt(4))

#define NBLOCKS (NCB / 128)        // 32 partial-argmax slices

// ---------------- scratch (device globals; no runtime allocation) -----------
__device__ __nv_bfloat16 g_AcbS[(size_t)NCB * KSPLIT];         // cb split [hi|lo|hi]
__device__ __nv_bfloat16 g_HsS [(size_t)BATCH * TDIM * KSPLIT];// hs^T split [hi|lo|hi]
__device__ __nv_bfloat16 g_WTS [3][(size_t)CDIM * KSPLIT];     // Wq,Wk,Wv^T split [hi|hi|lo]
__device__ __nv_bfloat16 g_KpS[(size_t)NCB * KSPLIT];          // K' split [hi|lo|hi]
__device__ __nv_bfloat16 g_QgS[(size_t)BATCH * TDIM * KSPLIT]; // Qg split [hi|hi|lo]
__device__ float g_V [(size_t)NCB * CDIM];
__device__ float g_cg[(size_t)BATCH * TDIM * HH];
__device__ int   g_idx[(size_t)BATCH * TDIM];
__device__ float g_pmax[NBLOCKS * BATCH * TDIM];
__device__ int   g_pidx[NBLOCKS * BATCH * TDIM];

// ======================= helpers ============================================
#define SMEM_SWIZZLE_128B(off) ((off) ^ (((off) >> 3) & 0x70))
#define CP_ASYNC16(dst, src) \
    asm volatile("cp.async.cg.shared.global [%0], [%1], 16;" :: "r"(dst), "l"(src))
#define CP_ASYNC_COMMIT() asm volatile("cp.async.commit_group;" ::: "memory")

__device__ __forceinline__ uint32_t smem_to_u32(const void* p) {
    uint32_t a;
    asm("{ .reg .u64 t; cvta.to.shared.u64 t, %1; cvt.u32.u64 %0, t; }"
        : "=r"(a) : "l"(p));
    return a;
}
__device__ __forceinline__ void ldsm_x4(uint32_t& r0, uint32_t& r1, uint32_t& r2,
                                        uint32_t& r3, uint32_t addr) {
    asm volatile("ldmatrix.sync.aligned.m8n8.x4.shared.b16 {%0,%1,%2,%3}, [%4];"
                 : "=r"(r0), "=r"(r1), "=r"(r2), "=r"(r3) : "r"(addr));
}
__device__ __forceinline__ void mma16816(float* c, uint32_t a0, uint32_t a1,
                                         uint32_t a2, uint32_t a3,
                                         uint32_t b0, uint32_t b1) {
    asm volatile(
        "mma.sync.aligned.m16n8k16.row.col.f32.bf16.bf16.f32 "
        "{%0,%1,%2,%3}, {%4,%5,%6,%7}, {%8,%9}, {%0,%1,%2,%3};"
        : "+f"(c[0]), "+f"(c[1]), "+f"(c[2]), "+f"(c[3])
        : "r"(a0), "r"(a1), "r"(a2), "r"(a3), "r"(b0), "r"(b1));
}
__device__ __forceinline__ void split2bf(float v0, float v1, unsigned& hu, unsigned& lu) {
    __nv_bfloat16 h0 = __float2bfloat16(v0), h1 = __float2bfloat16(v1);
    float r0 = v0 - __bfloat162float(h0), r1 = v1 - __bfloat162float(h1);
    __nv_bfloat16 l0 = __float2bfloat16(r0), l1 = __float2bfloat16(r1);
    __nv_bfloat162 ph = __halves2bfloat162(h0, h1);
    __nv_bfloat162 pl = __halves2bfloat162(l0, l1);
    hu = *reinterpret_cast<unsigned*>(&ph);
    lu = *reinterpret_cast<unsigned*>(&pl);
}
__device__ __forceinline__ void split1bf(float v, __nv_bfloat16& h, __nv_bfloat16& l) {
    h = __float2bfloat16(v);
    l = __float2bfloat16(v - __bfloat162float(h));
}

// =================== canonical K=1536 bf16 mma core =========================
// A: 128 rows (K-major, 1536 cols = 3072 B); B: 128 rows (K-major).
// acc[mi*4+nj][f]: row r = wm*64+mi*16+(lane>>2)+(f>=2?8:0),
//                  col c = wn*32+nj*8+2*(lane&3)+(f&1)
#define GEMM_STAGE  32768                    // A 16KB + B 16KB
#define GEMM_SMEM   (3 * GEMM_STAGE)         // 98304
#define GEMM_CHUNKS (KSPLIT / 64)            // 24

__device__ __forceinline__ void gemm1536_core(const char* Abase, const char* Bbase,
                                              uint32_t sb, int tid,
                                              float (&acc)[16][4]) {
    const int lane = tid & 31;
    const int wid  = tid >> 5;
    const int wm = wid & 1, wn = wid >> 1;

    #define GISSUE(c) do { \
        int _s = (c) % 3; \
        uint32_t _as = sb + _s * GEMM_STAGE; \
        uint32_t _bs = _as + 16384; \
        size_t _ko = (size_t)(c) * 128; \
        _Pragma("unroll") \
        for (int _i = 0; _i < 4; _i++) { \
            int _u = tid + _i * 256; \
            int _r = _u >> 3, _c16 = (_u & 7) * 16; \
            CP_ASYNC16(_as + SMEM_SWIZZLE_128B(_r * 128 + _c16), \
                       Abase + (size_t)_r * 3072 + _ko + _c16); \
        } \
        _Pragma("unroll") \
        for (int _i = 0; _i < 4; _i++) { \
            int _u = tid + _i * 256; \
            int _r = _u >> 3, _c16 = (_u & 7) * 16; \
            CP_ASYNC16(_bs + SMEM_SWIZZLE_128B(_r * 128 + _c16), \
                       Bbase + (size_t)_r * 3072 + _ko + _c16); \
        } \
        CP_ASYNC_COMMIT(); \
    } while (0)

    GISSUE(0);
    GISSUE(1);

    for (int c = 0; c < GEMM_CHUNKS; c++) {
        if (c < GEMM_CHUNKS - 1) asm volatile("cp.async.wait_group 1;" ::: "memory");
        else                     asm volatile("cp.async.wait_group 0;" ::: "memory");
        __syncthreads();
        if (c + 2 < GEMM_CHUNKS) GISSUE(c + 2);   // buffer (c-1)%3 is free

        uint32_t As = sb + (c % 3) * GEMM_STAGE;
        uint32_t Bs = As + 16384;

        #pragma unroll
        for (int kk = 0; kk < 4; kk++) {
            uint32_t a[4][4];
            #pragma unroll
            for (int mi = 0; mi < 4; mi++) {
                int row = wm * 64 + mi * 16 + (lane & 15);
                int u   = kk * 2 + (lane >> 4);
                ldsm_x4(a[mi][0], a[mi][1], a[mi][2], a[mi][3],
                        As + row * 128 + ((u ^ (row & 7)) << 4));
            }
            uint32_t bf[2][4];
            #pragma unroll
            for (int nf = 0; nf < 2; nf++) {
                int row = wn * 32 + nf * 16 + ((lane >> 4) << 3) + (lane & 7);
                int u   = kk * 2 + ((lane >> 3) & 1);
                ldsm_x4(bf[nf][0], bf[nf][1], bf[nf][2], bf[nf][3],
                        Bs + row * 128 + ((u ^ (row & 7)) << 4));
            }
            #pragma unroll
            for (int mi = 0; mi < 4; mi++)
                #pragma unroll
                for (int nj = 0; nj < 4; nj++)
                    mma16816(acc[mi * 4 + nj],
                             a[mi][0], a[mi][1], a[mi][2], a[mi][3],
                             bf[nj >> 1][(nj & 1) * 2], bf[nj >> 1][(nj & 1) * 2 + 1]);
        }
    }
    #undef GISSUE
}

// ===================== prep kernels =========================================
// cb [N,512] fp32 -> g_AcbS [N,1536] (hi|lo|hi)
__global__ void split_cb_kernel(const float* __restrict__ cb) {
    int idx = blockIdx.x * 256 + threadIdx.x;      // N*128 total
    int n  = idx >> 7;
    int c4 = (idx & 127) * 4;
    float4 v = *(const float4*)(cb + (size_t)n * CDIM + c4);
    unsigned h0, l0, h1, l1;
    split2bf(v.x, v.y, h0, l0);
    split2bf(v.z, v.w, h1, l1);
    __nv_bfloat16* op = g_AcbS + (size_t)n * KSPLIT + c4;
    *(uint2*)(op)        = make_uint2(h0, h1);
    *(uint2*)(op + 512)  = make_uint2(l0, l1);
    *(uint2*)(op + 1024) = make_uint2(h0, h1);
}

// W [512 in,512 out] fp32 -> g_WTS[z] [c][1536] (hi|hi|lo); z: 0=Wq 1=Wk 2=Wv
__global__ void wsplit_kernel(const float* __restrict__ Wq,
                              const float* __restrict__ Wk,
                              const float* __restrict__ Wv) {
    const float* W = (blockIdx.z == 0) ? Wq : (blockIdx.z == 1) ? Wk : Wv;
    __shared__ float tile[32][33];
    int ci0 = blockIdx.y * 32, c0 = blockIdx.x * 32;
    int tx = threadIdx.x & 31, ty = threadIdx.x >> 5;     // ty 0..7
    #pragma unroll
    for (int k = 0; k < 4; k++)
        tile[ty + 8 * k][tx] = W[(size_t)(ci0 + ty + 8 * k) * CDIM + c0 + tx];
    __syncthreads();
    __nv_bfloat16* base = g_WTS[blockIdx.z];
    #pragma unroll
    for (int k = 0; k < 4; k++) {
        int c = c0 + ty + 8 * k;
        float v = tile[tx][ty + 8 * k];
        __nv_bfloat16 h, l; split1bf(v, h, l);
        __nv_bfloat16* op = base + (size_t)c * KSPLIT + ci0 + tx;
        op[0] = h; op[512] = h; op[1024] = l;
    }
}

// hidden [B,512,2048] fp32 -> g_HsS [(b*T+t)][1536] (hi|lo|hi)
__global__ void hsplit_kernel(const float* __restrict__ hidden) {
    int b = blockIdx.z;
    __shared__ float tile[32][33];
    int ci0 = blockIdx.y * 32, t0 = blockIdx.x * 32;
    int tx = threadIdx.x & 31, ty = threadIdx.x >> 5;
    const float* hp = hidden + (size_t)b * CDIM * TDIM;
    #pragma unroll
    for (int k = 0; k < 4; k++)
        tile[ty + 8 * k][tx] = hp[(size_t)(ci0 + ty + 8 * k) * TDIM + t0 + tx];
    __syncthreads();
    #pragma unroll
    for (int k = 0; k < 4; k++) {
        int t = t0 + ty + 8 * k;
        float v = tile[tx][ty + 8 * k];
        __nv_bfloat16 h, l; split1bf(v, h, l);
        __nv_bfloat16* op = g_HsS + ((size_t)b * TDIM + t) * KSPLIT + ci0 + tx;
        op[0] = h; op[512] = l; op[1024] = h;
    }
}

// cg[bt][h] = sum_ci (hs_hi+hs_lo)(ci) * Wp[ci][h] + bp[h]
__global__ void cg2_kernel(const float* __restrict__ Wp, const float* __restrict__ bp) {
    __shared__ float sWp[CDIM * HH];
    #pragma unroll
    for (int i = 0; i < 8; i++)
        sWp[threadIdx.x + i * 256] = Wp[threadIdx.x + i * 256];
    __syncthreads();
    int w = threadIdx.x >> 5, lane = threadIdx.x & 31;
    int bt = blockIdx.x * 8 + w;
    const __nv_bfloat16* row = g_HsS + (size_t)bt * KSPLIT;
    float a0 = 0, a1 = 0, a2 = 0, a3 = 0;
    for (int ci = lane; ci < CDIM; ci += 32) {
        float x = __bfloat162float(row[ci]) + __bfloat162float(row[512 + ci]);
        a0 += x * sWp[ci * 4 + 0];
        a1 += x * sWp[ci * 4 + 1];
        a2 += x * sWp[ci * 4 + 2];
        a3 += x * sWp[ci * 4 + 3];
    }
    #pragma unroll
    for (int off = 16; off; off >>= 1) {
        a0 += __shfl_xor_sync(0xffffffff, a0, off);
        a1 += __shfl_xor_sync(0xffffffff, a1, off);
        a2 += __shfl_xor_sync(0xffffffff, a2, off);
        a3 += __shfl_xor_sync(0xffffffff, a3, off);
    }
    if (lane == 0) {
        g_cg[(size_t)bt * 4 + 0] = a0 + bp[0];
        g_cg[(size_t)bt * 4 + 1] = a1 + bp[1];
        g_cg[(size_t)bt * 4 + 2] = a2 + bp[2];
        g_cg[(size_t)bt * 4 + 3] = a3 + bp[3];
    }
}

// ===================== projection GEMMs (tensor) ============================
// z=0: K' = cb@Wk + bk -> split to g_KpS ; z=1: V = cb@Wv + bv -> fp32 g_V
__global__ __launch_bounds__(256, 2)
void gemm_proj_kv(const float* __restrict__ bk, const float* __restrict__ bv) {
    extern __shared__ __align__(1024) char smem[];
    const int tid = threadIdx.x;
    const int lane = tid & 31, wid = tid >> 5;
    const int wm = wid & 1, wn = wid >> 1;
    const int z = blockIdx.z;
    const int nBase = blockIdx.y * 128;
    const int cBase = blockIdx.x * 128;
    const uint32_t sb = smem_to_u32(smem);

    float acc[16][4] = {};
    gemm1536_core((const char*)(g_AcbS + (size_t)nBase * KSPLIT),
                  (const char*)(g_WTS[1 + z] + (size_t)cBase * KSPLIT),
                  sb, tid, acc);

    const float* bias = z ? bv : bk;
    #pragma unroll
    for (int mi = 0; mi < 4; mi++) {
        #pragma unroll
        for (int nj = 0; nj < 4; nj++) {
            float* A = acc[mi * 4 + nj];
            int r  = wm * 64 + mi * 16 + (lane >> 2);
            int cc = cBase + wn * 32 + nj * 8 + 2 * (lane & 3);
            float b0 = bias[cc], b1 = bias[cc + 1];
            if (z == 0) {
                unsigned h, l;
                split2bf(A[0] + b0, A[1] + b1, h, l);
                __nv_bfloat16* op = g_KpS + (size_t)(nBase + r) * KSPLIT + cc;
                *(unsigned*)(op) = h; *(unsigned*)(op + 512) = l; *(unsigned*)(op + 1024) = h;
                split2bf(A[2] + b0, A[3] + b1, h, l);
                op = g_KpS + (size_t)(nBase + r + 8) * KSPLIT + cc;
                *(unsigned*)(op) = h; *(unsigned*)(op + 512) = l; *(unsigned*)(op + 1024) = h;
            } else {
                *(float2*)(g_V + (size_t)(nBase + r) * CDIM + cc) =
                    make_float2(A[0] + b0, A[1] + b1);
                *(float2*)(g_V + (size_t)(nBase + r + 8) * CDIM + cc) =
                    make_float2(A[2] + b0, A[3] + b1);
            }
        }
    }
}

// Qg = (hs@Wq + bq) * cg * CSCALE -> split to g_QgS [hi|hi|lo]
__global__ __launch_bounds__(256, 2)
void gemm_proj_q(const float* __restrict__ bq) {
    extern __shared__ __align__(1024) char smem[];
    const int tid = threadIdx.x;
    const int lane = tid & 31, wid = tid >> 5;
    const int wm = wid & 1, wn = wid >> 1;
    const int btBase = blockIdx.y * 128;
    const int cBase  = blockIdx.x * 128;     // head h = blockIdx.x
    const int h = blockIdx.x;
    const uint32_t sb = smem_to_u32(smem);

    float acc[16][4] = {};
    gemm1536_core((const char*)(g_HsS + (size_t)btBase * KSPLIT),
                  (const char*)(g_WTS[0] + (size_t)cBase * KSPLIT),
                  sb, tid, acc);

    #pragma unroll
    for (int mi = 0; mi < 4; mi++) {
        #pragma unroll
        for (int nj = 0; nj < 4; nj++) {
            float* A = acc[mi * 4 + nj];
            int r  = wm * 64 + mi * 16 + (lane >> 2);
            int cc = cBase + wn * 32 + nj * 8 + 2 * (lane & 3);
            float b0 = bq[cc], b1 = bq[cc + 1];
            int bt0 = btBase + r, bt1 = btBase + r + 8;
            float g0 = g_cg[(size_t)bt0 * 4 + h] * CSCALE;
            float g1 = g_cg[(size_t)bt1 * 4 + h] * CSCALE;
            unsigned hh, ll;
            split2bf((A[0] + b0) * g0, (A[1] + b1) * g0, hh, ll);
            __nv_bfloat16* op = g_QgS + (size_t)bt0 * KSPLIT + cc;
            *(unsigned*)(op) = hh; *(unsigned*)(op + 512) = hh; *(unsigned*)(op + 1024) = ll;
            split2bf((A[2] + b0) * g1, (A[3] + b1) * g1, hh, ll);
            op = g_QgS + (size_t)bt1 * KSPLIT + cc;
            *(unsigned*)(op) = hh; *(unsigned*)(op + 512) = hh; *(unsigned*)(op + 1024) = ll;
        }
    }
}

// ===================== logits GEMM + fused argmax ===========================
__global__ __launch_bounds__(256, 2)
void gemm_logits_mma(float* __restrict__ out) {
    extern __shared__ __align__(1024) char smem[];
    const int tid  = threadIdx.x;
    const int wid  = tid >> 5, lane = tid & 31;
    const int wm   = wid & 1;
    const int wn   = wid >> 1;
    const int b     = blockIdx.z;
    const int nBase = blockIdx.y * 128;
    const int tBase = blockIdx.x * 128;
    const uint32_t sb = smem_to_u32(smem);

    float acc[16][4] = {};
    gemm1536_core((const char*)(g_KpS + (size_t)nBase * KSPLIT),
                  (const char*)(g_QgS + ((size_t)b * TDIM + tBase) * KSPLIT),
                  sb, tid, acc);

    __syncthreads();   // smem free; safe to alias for argmax below

    // ---- write logits ----
    float* obase = out + (size_t)b * NCB * TDIM + (size_t)nBase * TDIM + tBase;
    #pragma unroll
    for (int mi = 0; mi < 4; mi++) {
        #pragma unroll
        for (int nj = 0; nj < 4; nj++) {
            float* A = acc[mi * 4 + nj];
            int r  = wm * 64 + mi * 16 + (lane >> 2);
            int cc = wn * 32 + nj * 8 + 2 * (lane & 3);
            *(float2*)(obase + (size_t)r * TDIM + cc)       = make_float2(A[0], A[1]);
            *(float2*)(obase + (size_t)(r + 8) * TDIM + cc) = make_float2(A[2], A[3]);
        }
    }

    // ---- fused argmax partial over this CTA's 128 rows ----
    float mv[8]; int mi_[8];
    #pragma unroll
    for (int nj = 0; nj < 4; nj++) {
        #pragma unroll
        for (int cc = 0; cc < 2; cc++) {
            int key = nj * 2 + cc;
            float best = -INFINITY; int bidx = 0;
            #pragma unroll
            for (int mi = 0; mi < 4; mi++) {
                #pragma unroll
                for (int hf = 0; hf < 2; hf++) {
                    float v = acc[mi * 4 + nj][hf * 2 + cc];
                    int   ix = nBase + wm * 64 + mi * 16 + (lane >> 2) + hf * 8;
                    if (v > best || (v == best && ix < bidx)) { best = v; bidx = ix; }
                }
            }
            mv[key] = best; mi_[key] = bidx;
        }
    }
    #pragma unroll
    for (int off = 4; off < 32; off <<= 1) {
        #pragma unroll
        for (int key = 0; key < 8; key++) {
            float ov = __shfl_xor_sync(0xffffffff, mv[key], off);
            int   oi = __shfl_xor_sync(0xffffffff, mi_[key], off);
            if (ov > mv[key] || (ov == mv[key] && oi < mi_[key])) {
                mv[key] = ov; mi_[key] = oi;
            }
        }
    }
    float* sval = (float*)smem;               // [2][128]
    int*   sidx = (int*)(smem + 2 * 128 * 4); // [2][128]
    if (lane < 4) {
        #pragma unroll
        for (int nj = 0; nj < 4; nj++)
            #pragma unroll
            for (int cc = 0; cc < 2; cc++) {
                int col = wn * 32 + nj * 8 + 2 * lane + cc;
                sval[wm * 128 + col] = mv[nj * 2 + cc];
                sidx[wm * 128 + col] = mi_[nj * 2 + cc];
            }
    }
    __syncthreads();
    if (tid < 128) {
        float v0 = sval[tid],      v1 = sval[128 + tid];
        int   i0 = sidx[tid],      i1 = sidx[128 + tid];
        bool take1 = (v1 > v0) || (v1 == v0 && i1 < i0);
        size_t o = ((size_t)blockIdx.y * BATCH + b) * TDIM + tBase + tid;
        g_pmax[o] = take1 ? v1 : v0;
        g_pidx[o] = take1 ? i1 : i0;
    }
}

// ---------------- final argmax over the 32 slices ---------------------------
__global__ void argmax_final_kernel(float* __restrict__ idx_out) {
    int b = blockIdx.y;
    int t = blockIdx.x * 256 + threadIdx.x;
    float best = -INFINITY; int bi = 0x7fffffff;
    #pragma unroll
    for (int z = 0; z < NBLOCKS; z++) {
        float x = g_pmax[((size_t)z * BATCH + b) * TDIM + t];
        int  ii = g_pidx[((size_t)z * BATCH + b) * TDIM + t];
        if (x > best || (x == best && ii < bi)) { best = x; bi = ii; }
    }
    g_idx[b * TDIM + t] = bi;
    idx_out[b * TDIM + t] = (float)bi;
}

// ---------------- z_q gather: z_q[b,c,t] = V[idx[b,t], c] -------------------
__global__ void zq_kernel(float* __restrict__ zq) {
    int b = blockIdx.y;
    int lane = threadIdx.x & 31;
    int cgrp = threadIdx.x >> 5;
    int t = blockIdx.x * 32 + lane;
    int row = g_idx[b * TDIM + t];
    const float* v = g_V + (size_t)row * CDIM;
    float* o = zq + (size_t)b * CDIM * TDIM + t;
    int c0 = cgrp * 64;
    #pragma unroll 8
    for (int c = c0; c < c0 + 64; c++)
        o[(size_t)c * TDIM] = __ldg(&v[c]);
}

// ---------------- launcher --------------------------------------------------
extern "C" void kernel_launch(void* const* d_in, const int* in_sizes, int n_in,
                              void* d_out, int out_size) {
    const float* hidden = (const float*)d_in[0];  // [B,C,T]
    const float* cb     = (const float*)d_in[1];  // [N,C]
    const float* Wq = (const float*)d_in[2]; const float* bq = (const float*)d_in[3];
    const float* Wk = (const float*)d_in[4]; const float* bk = (const float*)d_in[5];
    const float* Wv = (const float*)d_in[6]; const float* bv = (const float*)d_in[7];
    const float* Wp = (const float*)d_in[8]; const float* bp = (const float*)d_in[9];

    float* out        = (float*)d_out;
    float* out_logits = out;                                       // B*N*T
    float* out_idx    = out + (size_t)BATCH * NCB * TDIM;          // B*T
    float* out_zq     = out_idx + (size_t)BATCH * TDIM;            // B*C*T

    cudaFuncSetAttribute(gemm_proj_kv,
                         cudaFuncAttributeMaxDynamicSharedMemorySize, GEMM_SMEM);
    cudaFuncSetAttribute(gemm_proj_q,
                         cudaFuncAttributeMaxDynamicSharedMemorySize, GEMM_SMEM);
    cudaFuncSetAttribute(gemm_logits_mma,
                         cudaFuncAttributeMaxDynamicSharedMemorySize, GEMM_SMEM);

    // prep: splits + transposes
    split_cb_kernel<<<NCB * 128 / 256, 256>>>(cb);
    wsplit_kernel<<<dim3(16, 16, 3), 256>>>(Wq, Wk, Wv);
    hsplit_kernel<<<dim3(TDIM / 32, CDIM / 32, BATCH), 256>>>(hidden);
    // head gates from transposed hidden
    cg2_kernel<<<BATCH * TDIM / 8, 256>>>(Wp, bp);
    // projections on tensor cores
    gemm_proj_kv<<<dim3(4, NCB / 128, 2), 256, GEMM_SMEM>>>(bk, bv);
    gemm_proj_q<<<dim3(4, BATCH * TDIM / 128), 256, GEMM_SMEM>>>(bq);
    // logits + fused argmax partials
    gemm_logits_mma<<<dim3(TDIM / 128, NCB / 128, BATCH), 256, GEMM_SMEM>>>(out_logits);
    // final argmax + z_q gather
    argmax_final_kernel<<<dim3(TDIM / 256, BATCH), 256>>>(out_idx);
    zq_kernel<<<dim3(TDIM / 32, BATCH), 256>>>(out_zq);
}